// round 5
// baseline (speedup 1.0000x reference)
#include <cuda_runtime.h>

// VanillaRNN persistent kernel for GB300 (sm_103a) — round 4.
// h_{t+1} = tanh(W_hx * x_t + W_hh @ h_t + b_h), 1024 steps, then p = W_ph @ h + b_p.
//
// 128 persistent CTAs = 16 row-groups x 8 batch-groups, 32x32 output tile each.
// Round-4 changes vs best (R1, 9172us):
//  - 512 threads/CTA (16 warps, 4/SMSP) for latency hiding; 2 outputs/thread.
//  - Barrier is per-BATCH-GROUP (16 CTAs), not grid-wide (128): a CTA only
//    consumes h columns produced by CTAs of its own batch group.
//  - Plain scalar FFMA inner loop (f32x2 regressed in R3).

#define HH    512
#define BB    256
#define TT    1024
#define NCLS  10

#define RGN   16
#define BGN   8
#define HR    32            // rows per CTA
#define BT    32            // batch cols per CTA
#define NCTA  (RGN * BGN)   // 128
#define NTHR  512

#define W_PAD 516           // W row stride in floats (512 + 4), 16B aligned
#define H_PAD 36            // hs row stride in floats (32 + 4),  16B aligned

#define SMEM_FLOATS (HR * W_PAD + HH * H_PAD + BT)
#define SMEM_BYTES  (SMEM_FLOATS * 4)

__device__ float    g_h[2][HH][BB];   // double-buffered hidden state
__device__ unsigned g_bar[BGN];       // per-batch-group barrier counters

__global__ void __launch_bounds__(NTHR, 1) rnn_persistent(
    const float* __restrict__ x,       // [BB][TT]
    const float* __restrict__ h_init,  // [HH]
    const float* __restrict__ W_hx,    // [HH]
    const float* __restrict__ W_hh,    // [HH][HH]
    const float* __restrict__ b_h,     // [HH]
    const float* __restrict__ W_ph,    // [NCLS][HH]
    const float* __restrict__ b_p,     // [NCLS]
    float* __restrict__ out)           // [BB][NCLS]
{
    extern __shared__ float smem[];
    float* Wr = smem;                  // [HR][W_PAD]
    float* hs = smem + HR * W_PAD;     // [HH][H_PAD]
    float* xs = hs + HH * H_PAD;       // [BT]

    const int tid   = threadIdx.x;
    const int cta   = blockIdx.x;
    const int rg    = cta >> 3;
    const int bg    = cta & 7;
    const int rbase = rg * HR;
    const int cbase = bg * BT;

    // ---- load resident W_hh slice (32 rows x 512) ----
    for (int i = tid; i < HR * (HH / 4); i += NTHR) {
        int r  = i >> 7;
        int kq = i & 127;
        float4 v = *reinterpret_cast<const float4*>(W_hh + (rbase + r) * HH + (kq << 2));
        *reinterpret_cast<float4*>(Wr + r * W_PAD + (kq << 2)) = v;
    }

    // ---- init hs with h_init broadcast ----
    for (int k = tid; k < HH; k += NTHR) {
        float v = h_init[k];
        float* row = hs + k * H_PAD;
        #pragma unroll
        for (int c = 0; c < BT; ++c) row[c] = v;
    }

    // ---- per-thread mapping: 1 row x 1 col-pair (2 outputs) ----
    // lane 0-15: row 2w, lanes 16-31: row 2w+1 -> W loads broadcast 16-wide.
    const int r  = tid >> 4;           // 0..31
    const int c0 = (tid & 15) << 1;    // 0,2,..,30

    const float bh = b_h[rbase + r];
    const float wx = W_hx[rbase + r];

    const float* wp  = Wr + r * W_PAD;
    const float* hcp = hs + c0;

    __syncthreads();

    for (int s = 0; s < TT; ++s) {
        // ---- refresh h tile from global (written by same-bg CTAs last step) ----
        if (s > 0) {
            const int buf = s & 1;
            #pragma unroll
            for (int i = tid; i < HH * (BT / 4); i += NTHR) {
                int k  = i >> 3;
                int cq = i & 7;
                float4 v = __ldcg(reinterpret_cast<const float4*>(
                               &g_h[buf][k][cbase + (cq << 2)]));
                *reinterpret_cast<float4*>(hs + k * H_PAD + (cq << 2)) = v;
            }
        }
        if (tid < BT) xs[tid] = x[(cbase + tid) * TT + s];
        __syncthreads();

        float a0 = fmaf(wx, xs[c0],     bh);
        float a1 = fmaf(wx, xs[c0 + 1], bh);

        // ---- 512-deep dot products, 2 outputs per thread ----
        #pragma unroll 16
        for (int k = 0; k < HH; k += 4) {
            const float4 w4 = *reinterpret_cast<const float4*>(wp + k);
            const float2 h0 = *reinterpret_cast<const float2*>(hcp + (k + 0) * H_PAD);
            const float2 h1 = *reinterpret_cast<const float2*>(hcp + (k + 1) * H_PAD);
            const float2 h2 = *reinterpret_cast<const float2*>(hcp + (k + 2) * H_PAD);
            const float2 h3 = *reinterpret_cast<const float2*>(hcp + (k + 3) * H_PAD);
            a0 = fmaf(w4.x, h0.x, a0); a1 = fmaf(w4.x, h0.y, a1);
            a0 = fmaf(w4.y, h1.x, a0); a1 = fmaf(w4.y, h1.y, a1);
            a0 = fmaf(w4.z, h2.x, a0); a1 = fmaf(w4.z, h2.y, a1);
            a0 = fmaf(w4.w, h3.x, a0); a1 = fmaf(w4.w, h3.y, a1);
        }

        a0 = tanhf(a0);
        a1 = tanhf(a1);

        const int wbuf = (s + 1) & 1;
        *reinterpret_cast<float2*>(&g_h[wbuf][rbase + r][cbase + c0]) =
            make_float2(a0, a1);

        // ---- per-batch-group barrier (16 CTAs share one counter) ----
        __threadfence();
        __syncthreads();
        if (tid == 0) {
            atomicAdd(&g_bar[bg], 1u);
            const unsigned target = (unsigned)RGN * (unsigned)(s + 1);
            while (*((volatile unsigned*)&g_bar[bg]) < target) { }
            __threadfence();
        }
        __syncthreads();
    }

    // ---- final projection on row-group 0 CTAs ----
    if (rg == 0) {
        float* Wp = smem;  // reuse W region for W_ph (10*512 floats)
        for (int i = tid; i < (NCLS * HH) / 4; i += NTHR) {
            float4 v = *reinterpret_cast<const float4*>(W_ph + (i << 2));
            *reinterpret_cast<float4*>(Wp + (i << 2)) = v;
        }
        for (int i = tid; i < HH * (BT / 4); i += NTHR) {
            int k = i >> 3, cq = i & 7;
            float4 v = __ldcg(reinterpret_cast<const float4*>(
                           &g_h[0][k][cbase + (cq << 2)]));
            *reinterpret_cast<float4*>(hs + k * H_PAD + (cq << 2)) = v;
        }
        __syncthreads();
        for (int idx = tid; idx < BT * NCLS; idx += NTHR) {
            int cl = idx / NCLS;
            int n  = idx - cl * NCLS;
            float acc = b_p[n];
            const float* wrow = Wp + n * HH;
            const float* hcol = hs + cl;
            #pragma unroll 8
            for (int k = 0; k < HH; ++k)
                acc = fmaf(wrow[k], hcol[k * H_PAD], acc);
            out[(cbase + cl) * NCLS + n] = acc;
        }
    }
}

extern "C" void kernel_launch(void* const* d_in, const int* in_sizes, int n_in,
                              void* d_out, int out_size) {
    const float* x      = (const float*)d_in[0];
    const float* h_init = (const float*)d_in[1];
    const float* W_hx   = (const float*)d_in[2];
    const float* W_hh   = (const float*)d_in[3];
    const float* b_h    = (const float*)d_in[4];
    const float* W_ph   = (const float*)d_in[5];
    const float* b_p    = (const float*)d_in[6];
    float* out = (float*)d_out;

    void* barp = nullptr;
    cudaGetSymbolAddress(&barp, g_bar);
    cudaMemsetAsync(barp, 0, BGN * sizeof(unsigned), 0);

    cudaFuncSetAttribute(rnn_persistent,
                         cudaFuncAttributeMaxDynamicSharedMemorySize, SMEM_BYTES);

    rnn_persistent<<<NCTA, NTHR, SMEM_BYTES, 0>>>(x, h_init, W_hx, W_hh, b_h,
                                                  W_ph, b_p, out);
}

// round 6
// speedup vs baseline: 1.0857x; 1.0857x over previous
#include <cuda_runtime.h>

// VanillaRNN persistent kernel for GB300 (sm_103a) — round 5: LDS-traffic cut.
// h_{t+1} = tanh(W_hx * x_t + W_hh @ h_t + b_h), 1024 steps, then p = W_ph @ h + b_p.
//
// 128 persistent CTAs = 16 row-groups x 8 batch-groups, 32x32 output tile each.
// Key change vs R1 (9172us best): thread (r, j) = (tid/8, tid%8) computes
// partial dots for row r over k in {k : k%32 in [4j,4j+4)} for ALL 32 columns.
//  - h stored TRANSPOSED in smem (hsT[col][k]) -> LDS.128 over k feeds 4 FMA,
//    1 wavefront/warp-instruction (8 distinct 16B chunks, 4-way broadcast).
//  - W float4 register reused across 32 columns -> W LDS 16/thread/step.
//  - 8-way k-partials reduced via padded smem scratch (within-warp, syncwarp).
// FMA:LDS instr ratio ~3.9 -> FFMA pipe (8192 cyc/step floor) becomes binding.

#define HH    512
#define BB    256
#define TT    1024
#define NCLS  10

#define RGN   16
#define BGN   8
#define HR    32
#define BT    32
#define NCTA  (RGN * BGN)
#define NTHR  256

#define W_PAD   516          // W row stride (floats)
#define HT_PAD  516          // hsT row stride (floats), k-dim padded
#define RED_PAD 36           // reduction scratch row stride (floats)

#define SMEM_FLOATS (HR * W_PAD + BT * HT_PAD + NTHR * RED_PAD + BT)
#define SMEM_BYTES  (SMEM_FLOATS * 4)   // ~169 KB

__device__ float    g_h[2][HH][BB];    // double-buffered hidden state
__device__ unsigned g_bar[BGN * 32];   // per-batch-group barriers, 128B apart

__global__ void __launch_bounds__(NTHR, 1) rnn_persistent(
    const float* __restrict__ x,       // [BB][TT]
    const float* __restrict__ h_init,  // [HH]
    const float* __restrict__ W_hx,    // [HH]
    const float* __restrict__ W_hh,    // [HH][HH]
    const float* __restrict__ b_h,     // [HH]
    const float* __restrict__ W_ph,    // [NCLS][HH]
    const float* __restrict__ b_p,     // [NCLS]
    float* __restrict__ out)           // [BB][NCLS]
{
    extern __shared__ float smem[];
    float* Wr  = smem;                      // [HR][W_PAD]
    float* hsT = Wr + HR * W_PAD;           // [BT][HT_PAD] transposed h
    float* red = hsT + BT * HT_PAD;         // [NTHR][RED_PAD] reduce scratch
    float* xs  = red + NTHR * RED_PAD;      // [BT]

    const int tid  = threadIdx.x;
    const int lane = tid & 31;
    const int wid  = tid >> 5;
    const int cta  = blockIdx.x;
    const int rg   = cta >> 3;
    const int bg   = cta & 7;
    const int rbase = rg * HR;
    const int cbase = bg * BT;

    const int r  = tid >> 3;      // 0..31 : row within tile
    const int j  = tid & 7;       // 0..7  : k-phase
    const int j4 = j << 2;

    // ---- load resident W_hh slice (32 rows x 512) ----
    for (int i = tid; i < HR * (HH / 4); i += NTHR) {
        int rr = i >> 7, kq = i & 127;
        float4 v = *reinterpret_cast<const float4*>(W_hh + (rbase + rr) * HH + (kq << 2));
        *reinterpret_cast<float4*>(Wr + rr * W_PAD + (kq << 2)) = v;
    }
    // ---- init hsT[c][k] = h_init[k] ----
    for (int i = tid; i < BT * (HH / 4); i += NTHR) {
        int c = i >> 7, kq = i & 127;
        float4 v = *reinterpret_cast<const float4*>(h_init + (kq << 2));
        *reinterpret_cast<float4*>(hsT + c * HT_PAD + (kq << 2)) = v;
    }

    const float bh = b_h[rbase + r];
    const float wx = W_hx[rbase + r];
    const float* wrow = Wr + r * W_PAD + j4;

    __syncthreads();

    for (int s = 0; s < TT; ++s) {
        // ---- refresh hsT (transposed) from global ----
        if (s > 0) {
            const int buf = s & 1;
            const float* gsrc = &g_h[buf][0][cbase + lane];
            #pragma unroll 4
            for (int it = 0; it < 16; ++it) {
                int k0 = (((it << 3) + wid) << 2);
                float4 v;
                v.x = __ldcg(gsrc + (k0 + 0) * BB);
                v.y = __ldcg(gsrc + (k0 + 1) * BB);
                v.z = __ldcg(gsrc + (k0 + 2) * BB);
                v.w = __ldcg(gsrc + (k0 + 3) * BB);
                *reinterpret_cast<float4*>(hsT + lane * HT_PAD + k0) = v;
            }
        }
        if (tid < BT) xs[tid] = x[(cbase + tid) * TT + s];
        __syncthreads();

        // ---- partial dots: 32 cols x 64 k-values per thread ----
        float acc[32];
        #pragma unroll
        for (int c = 0; c < 32; ++c) acc[c] = 0.f;

        #pragma unroll 2
        for (int i = 0; i < 16; ++i) {
            const float4 w = *reinterpret_cast<const float4*>(wrow + (i << 5));
            const float* hb = hsT + (i << 5) + j4;
            #pragma unroll
            for (int c = 0; c < 32; ++c) {
                const float4 h = *reinterpret_cast<const float4*>(hb + c * HT_PAD);
                acc[c] = fmaf(w.x, h.x, acc[c]);
                acc[c] = fmaf(w.y, h.y, acc[c]);
                acc[c] = fmaf(w.z, h.z, acc[c]);
                acc[c] = fmaf(w.w, h.w, acc[c]);
            }
        }

        // ---- reduce the 8 k-phase partials per (row, col) via smem ----
        float* myred = red + tid * RED_PAD;
        #pragma unroll
        for (int q = 0; q < 8; ++q)
            *reinterpret_cast<float4*>(myred + (q << 2)) =
                make_float4(acc[q * 4 + 0], acc[q * 4 + 1],
                            acc[q * 4 + 2], acc[q * 4 + 3]);
        __syncwarp();

        // lane (r, j) finalizes cols [4j, 4j+4) of row r
        const float* rrow = red + ((r << 3) * RED_PAD) + j4;
        float4 sum = *reinterpret_cast<const float4*>(rrow);
        #pragma unroll
        for (int jj = 1; jj < 8; ++jj) {
            float4 p = *reinterpret_cast<const float4*>(rrow + jj * RED_PAD);
            sum.x += p.x; sum.y += p.y; sum.z += p.z; sum.w += p.w;
        }

        const float4 xv = *reinterpret_cast<const float4*>(xs + j4);
        float4 o;
        o.x = tanhf(fmaf(wx, xv.x, sum.x + bh));
        o.y = tanhf(fmaf(wx, xv.y, sum.y + bh));
        o.z = tanhf(fmaf(wx, xv.z, sum.z + bh));
        o.w = tanhf(fmaf(wx, xv.w, sum.w + bh));

        const int wbuf = (s + 1) & 1;
        *reinterpret_cast<float4*>(&g_h[wbuf][rbase + r][cbase + j4]) = o;

        // ---- per-batch-group barrier (16 CTAs) ----
        __threadfence();
        __syncthreads();
        if (tid == 0) {
            atomicAdd(&g_bar[bg * 32], 1u);
            const unsigned target = (unsigned)RGN * (unsigned)(s + 1);
            while (*((volatile unsigned*)&g_bar[bg * 32]) < target) { }
            __threadfence();
        }
        __syncthreads();
    }

    // ---- final projection on row-group 0 CTAs ----
    // Final h is in g_h[0] (step 1023 wrote buffer (1023+1)&1 == 0).
    if (rg == 0) {
        const float* gsrc = &g_h[0][0][cbase + lane];
        #pragma unroll 4
        for (int it = 0; it < 16; ++it) {
            int k0 = (((it << 3) + wid) << 2);
            float4 v;
            v.x = __ldcg(gsrc + (k0 + 0) * BB);
            v.y = __ldcg(gsrc + (k0 + 1) * BB);
            v.z = __ldcg(gsrc + (k0 + 2) * BB);
            v.w = __ldcg(gsrc + (k0 + 3) * BB);
            *reinterpret_cast<float4*>(hsT + lane * HT_PAD + k0) = v;
        }
        __syncthreads();
        for (int idx = tid; idx < BT * NCLS; idx += NTHR) {
            int c = idx & 31;
            int n = idx >> 5;
            float accp = b_p[n];
            const float* wrow2 = W_ph + n * HH;
            const float* hc    = hsT + c * HT_PAD;
            #pragma unroll 4
            for (int k = 0; k < HH; k += 4) {
                float4 wv = *reinterpret_cast<const float4*>(wrow2 + k);
                float4 hv = *reinterpret_cast<const float4*>(hc + k);
                accp = fmaf(wv.x, hv.x, accp);
                accp = fmaf(wv.y, hv.y, accp);
                accp = fmaf(wv.z, hv.z, accp);
                accp = fmaf(wv.w, hv.w, accp);
            }
            out[(cbase + c) * NCLS + n] = accp;
        }
    }
}

extern "C" void kernel_launch(void* const* d_in, const int* in_sizes, int n_in,
                              void* d_out, int out_size) {
    const float* x      = (const float*)d_in[0];
    const float* h_init = (const float*)d_in[1];
    const float* W_hx   = (const float*)d_in[2];
    const float* W_hh   = (const float*)d_in[3];
    const float* b_h    = (const float*)d_in[4];
    const float* W_ph   = (const float*)d_in[5];
    const float* b_p    = (const float*)d_in[6];
    float* out = (float*)d_out;

    void* barp = nullptr;
    cudaGetSymbolAddress(&barp, g_bar);
    cudaMemsetAsync(barp, 0, BGN * 32 * sizeof(unsigned), 0);

    cudaFuncSetAttribute(rnn_persistent,
                         cudaFuncAttributeMaxDynamicSharedMemorySize, SMEM_BYTES);

    rnn_persistent<<<NCTA, NTHR, SMEM_BYTES, 0>>>(x, h_init, W_hx, W_hh, b_h,
                                                  W_ph, b_p, out);
}